// round 1
// baseline (speedup 1.0000x reference)
#include <cuda_runtime.h>
#include <math.h>

#define NNODES 50000
#define DIM    256
#define NH     4
#define NC     64
#define NEDGES 800000
#define EP     (NEDGES + NNODES)   // with self loops
#define NEG_SLOPE 0.2f
#define LN_EPS 1e-5f

#define SCAN_CHUNK 512
#define NCHUNK ((NNODES + SCAN_CHUNK - 1) / SCAN_CHUNK)  // 98

// ---------------- scratch (static device globals; no runtime alloc) ---------
__device__ float g_h[(size_t)NNODES * DIM];      // x @ W
__device__ float g_r[(size_t)NNODES * DIM];      // x @ W_res
__device__ float g_al_src[NNODES * NH];
__device__ float g_al_dst[NNODES * NH];
__device__ int   g_count[NNODES];
__device__ int   g_scan[NNODES];
__device__ int   g_bsum[NCHUNK];
__device__ int   g_boff[NCHUNK];
__device__ int   g_rowptr[NNODES + 1];
__device__ int   g_cursor[NNODES];
__device__ int   g_csr_src[EP];
__device__ float g_csr_e[(size_t)EP * NH];
__device__ int   g_is64;

__device__ __forceinline__ float lrelu(float x) { return x > 0.f ? x : NEG_SLOPE * x; }

// edge_index accessor handling int64-vs-int32 ambiguity
__device__ __forceinline__ int edge_at(const void* ei, long long idx) {
    if (g_is64) return (int)((const long long*)ei)[idx];
    return ((const int*)ei)[idx];
}

// ---------------- dtype detection ----------------
__global__ void detect_kernel(const int* __restrict__ ei_words) {
    if (threadIdx.x == 0 && blockIdx.x == 0) {
        int all0 = 1;
        for (int i = 0; i < 128; i++) {
            if (ei_words[2 * i + 1] != 0) { all0 = 0; break; }
        }
        g_is64 = all0;  // int64 little-endian: high words of values < 50000 are 0
    }
}

// ---------------- SGEMM: C = A(MxK) * B(KxN), row-major ----------------
#define BM 128
#define BN 128
#define BK 8
#define TM 8
#define TN 8
__global__ __launch_bounds__(256) void sgemm_kernel(
    const float* __restrict__ A, const float* __restrict__ B, float* __restrict__ C,
    int M, int Nn, int K)
{
    __shared__ float As[BK][BM];
    __shared__ float Bs[BK][BN];
    int tid = threadIdx.x;
    int blockRow = blockIdx.y * BM;
    int blockCol = blockIdx.x * BN;

    int aRow = tid >> 1;          // 0..127
    int aCol = (tid & 1) * 4;     // 0 or 4
    int bRow = tid >> 5;          // 0..7
    int bCol = (tid & 31) * 4;    // 0..124
    int tRow = (tid >> 4) * TM;
    int tCol = (tid & 15) * TN;

    float acc[TM][TN];
    #pragma unroll
    for (int i = 0; i < TM; i++)
        #pragma unroll
        for (int j = 0; j < TN; j++) acc[i][j] = 0.f;

    float regM[TM], regN[TN];

    for (int k0 = 0; k0 < K; k0 += BK) {
        int gr = blockRow + aRow;
        float4 av = make_float4(0.f, 0.f, 0.f, 0.f);
        if (gr < M) av = *reinterpret_cast<const float4*>(&A[(size_t)gr * K + k0 + aCol]);
        As[aCol + 0][aRow] = av.x;
        As[aCol + 1][aRow] = av.y;
        As[aCol + 2][aRow] = av.z;
        As[aCol + 3][aRow] = av.w;

        float4 bv = *reinterpret_cast<const float4*>(&B[(size_t)(k0 + bRow) * Nn + blockCol + bCol]);
        *reinterpret_cast<float4*>(&Bs[bRow][bCol]) = bv;
        __syncthreads();

        #pragma unroll
        for (int k = 0; k < BK; k++) {
            #pragma unroll
            for (int i = 0; i < TM; i++) regM[i] = As[k][tRow + i];
            #pragma unroll
            for (int j = 0; j < TN; j++) regN[j] = Bs[k][tCol + j];
            #pragma unroll
            for (int i = 0; i < TM; i++)
                #pragma unroll
                for (int j = 0; j < TN; j++)
                    acc[i][j] = fmaf(regM[i], regN[j], acc[i][j]);
        }
        __syncthreads();
    }

    #pragma unroll
    for (int i = 0; i < TM; i++) {
        int gr = blockRow + tRow + i;
        if (gr < M) {
            #pragma unroll
            for (int j = 0; j < TN; j += 4) {
                float4 v = make_float4(acc[i][j], acc[i][j+1], acc[i][j+2], acc[i][j+3]);
                *reinterpret_cast<float4*>(&C[(size_t)gr * Nn + blockCol + tCol + j]) = v;
            }
        }
    }
}

// ---------------- per-node attention logits: al = einsum(h, a) ----------------
__global__ __launch_bounds__(256) void attn_logits_kernel(
    const float* __restrict__ a_src, const float* __restrict__ a_dst)
{
    int gwarp = (blockIdx.x * blockDim.x + threadIdx.x) >> 5;
    int lane = threadIdx.x & 31;
    if (gwarp >= NNODES) return;
    const float* hrow = g_h + (size_t)gwarp * DIM;
    #pragma unroll
    for (int hd = 0; hd < NH; hd++) {
        float v0 = hrow[hd * NC + lane];
        float v1 = hrow[hd * NC + 32 + lane];
        float ss = v0 * __ldg(&a_src[hd * NC + lane]) + v1 * __ldg(&a_src[hd * NC + 32 + lane]);
        float sd = v0 * __ldg(&a_dst[hd * NC + lane]) + v1 * __ldg(&a_dst[hd * NC + 32 + lane]);
        #pragma unroll
        for (int o = 16; o > 0; o >>= 1) {
            ss += __shfl_down_sync(0xffffffffu, ss, o);
            sd += __shfl_down_sync(0xffffffffu, sd, o);
        }
        if (lane == 0) {
            g_al_src[gwarp * NH + hd] = ss;
            g_al_dst[gwarp * NH + hd] = sd;
        }
    }
}

// ---------------- CSR build ----------------
__global__ void init_counts_kernel() {
    int i = blockIdx.x * blockDim.x + threadIdx.x;
    if (i < NNODES) g_count[i] = 1;  // self loop
}

__global__ void hist_kernel(const void* __restrict__ ei) {
    int i = blockIdx.x * blockDim.x + threadIdx.x;
    if (i < NEDGES) {
        int d = edge_at(ei, (long long)NEDGES + i);
        atomicAdd(&g_count[d], 1);
    }
}

__global__ __launch_bounds__(SCAN_CHUNK) void scan1_kernel() {
    __shared__ int s[SCAN_CHUNK];
    int i = blockIdx.x * SCAN_CHUNK + threadIdx.x;
    int v = (i < NNODES) ? g_count[i] : 0;
    s[threadIdx.x] = v;
    __syncthreads();
    for (int off = 1; off < SCAN_CHUNK; off <<= 1) {
        int t = s[threadIdx.x];
        int u = (threadIdx.x >= off) ? s[threadIdx.x - off] : 0;
        __syncthreads();
        s[threadIdx.x] = t + u;
        __syncthreads();
    }
    if (i < NNODES) g_scan[i] = s[threadIdx.x];
    if (threadIdx.x == SCAN_CHUNK - 1) g_bsum[blockIdx.x] = s[SCAN_CHUNK - 1];
}

__global__ void scan2_kernel() {
    if (threadIdx.x == 0 && blockIdx.x == 0) {
        int run = 0;
        for (int b = 0; b < NCHUNK; b++) { g_boff[b] = run; run += g_bsum[b]; }
    }
}

__global__ void scan3_kernel() {
    int i = blockIdx.x * blockDim.x + threadIdx.x;
    if (i >= NNODES) return;
    int cnt = g_count[i];
    int incl = g_scan[i] + g_boff[i / SCAN_CHUNK];
    int start = incl - cnt;
    g_rowptr[i] = start;
    g_cursor[i] = start + 1;
    // self loop at slot `start`
    g_csr_src[start] = i;
    float4 es = *reinterpret_cast<const float4*>(&g_al_src[i * NH]);
    float4 ed = *reinterpret_cast<const float4*>(&g_al_dst[i * NH]);
    float4 e = make_float4(lrelu(es.x + ed.x), lrelu(es.y + ed.y),
                           lrelu(es.z + ed.z), lrelu(es.w + ed.w));
    *reinterpret_cast<float4*>(&g_csr_e[(size_t)start * NH]) = e;
    if (i == NNODES - 1) g_rowptr[NNODES] = start + cnt;
}

__global__ void scatter_kernel(const void* __restrict__ ei) {
    int i = blockIdx.x * blockDim.x + threadIdx.x;
    if (i >= NEDGES) return;
    int s = edge_at(ei, i);
    int d = edge_at(ei, (long long)NEDGES + i);
    int pos = atomicAdd(&g_cursor[d], 1);
    g_csr_src[pos] = s;
    float4 es = *reinterpret_cast<const float4*>(&g_al_src[s * NH]);
    float4 ed = *reinterpret_cast<const float4*>(&g_al_dst[d * NH]);
    float4 e = make_float4(lrelu(es.x + ed.x), lrelu(es.y + ed.y),
                           lrelu(es.z + ed.z), lrelu(es.w + ed.w));
    *reinterpret_cast<float4*>(&g_csr_e[(size_t)pos * NH]) = e;
}

// ---------------- fused softmax + aggregate + residual + LayerNorm ----------
#define AGG_CH 128
__global__ __launch_bounds__(256) void aggregate_kernel(
    const float* __restrict__ bias_gat, const float* __restrict__ b_res,
    const float* __restrict__ gamma, const float* __restrict__ beta,
    float* __restrict__ out)
{
    int v = blockIdx.x;
    int tid = threadIdx.x;
    int start = g_rowptr[v];
    int end = g_rowptr[v + 1];
    int deg = end - start;  // >= 1 (self loop)

    __shared__ float s_m[NH], s_inv[NH];
    __shared__ int   s_src[AGG_CH];
    __shared__ float s_alpha[AGG_CH * NH];
    __shared__ float s_s[8], s_q[8];

    // --- softmax max + denom (warp 0 only; deg is small) ---
    if (tid < 32) {
        float m0 = -1e30f, m1 = -1e30f, m2 = -1e30f, m3 = -1e30f;
        for (int j = tid; j < deg; j += 32) {
            float4 e = *reinterpret_cast<const float4*>(&g_csr_e[(size_t)(start + j) * NH]);
            m0 = fmaxf(m0, e.x); m1 = fmaxf(m1, e.y);
            m2 = fmaxf(m2, e.z); m3 = fmaxf(m3, e.w);
        }
        #pragma unroll
        for (int o = 16; o > 0; o >>= 1) {
            m0 = fmaxf(m0, __shfl_xor_sync(0xffffffffu, m0, o));
            m1 = fmaxf(m1, __shfl_xor_sync(0xffffffffu, m1, o));
            m2 = fmaxf(m2, __shfl_xor_sync(0xffffffffu, m2, o));
            m3 = fmaxf(m3, __shfl_xor_sync(0xffffffffu, m3, o));
        }
        float d0 = 0.f, d1 = 0.f, d2 = 0.f, d3 = 0.f;
        for (int j = tid; j < deg; j += 32) {
            float4 e = *reinterpret_cast<const float4*>(&g_csr_e[(size_t)(start + j) * NH]);
            d0 += expf(e.x - m0); d1 += expf(e.y - m1);
            d2 += expf(e.z - m2); d3 += expf(e.w - m3);
        }
        #pragma unroll
        for (int o = 16; o > 0; o >>= 1) {
            d0 += __shfl_xor_sync(0xffffffffu, d0, o);
            d1 += __shfl_xor_sync(0xffffffffu, d1, o);
            d2 += __shfl_xor_sync(0xffffffffu, d2, o);
            d3 += __shfl_xor_sync(0xffffffffu, d3, o);
        }
        if (tid == 0) {
            s_m[0] = m0; s_m[1] = m1; s_m[2] = m2; s_m[3] = m3;
            s_inv[0] = 1.f / (d0 + 1e-16f);
            s_inv[1] = 1.f / (d1 + 1e-16f);
            s_inv[2] = 1.f / (d2 + 1e-16f);
            s_inv[3] = 1.f / (d3 + 1e-16f);
        }
    }
    __syncthreads();

    int hd = tid >> 6;  // head 0..3
    float acc = 0.f;

    for (int c0 = 0; c0 < deg; c0 += AGG_CH) {
        int len = min(AGG_CH, deg - c0);
        if (tid < len) s_src[tid] = g_csr_src[start + c0 + tid];
        for (int t = tid; t < len * NH; t += 256) {
            int j = t >> 2, h = t & 3;
            s_alpha[t] = expf(g_csr_e[(size_t)(start + c0 + j) * NH + h] - s_m[h]) * s_inv[h];
        }
        __syncthreads();

        int j = 0;
        for (; j + 4 <= len; j += 4) {
            int sa = s_src[j], sb = s_src[j+1], sc = s_src[j+2], sd = s_src[j+3];
            float a0 = s_alpha[((j    ) << 2) | hd];
            float a1 = s_alpha[((j + 1) << 2) | hd];
            float a2 = s_alpha[((j + 2) << 2) | hd];
            float a3 = s_alpha[((j + 3) << 2) | hd];
            float h0 = g_h[(size_t)sa * DIM + tid];
            float h1 = g_h[(size_t)sb * DIM + tid];
            float h2 = g_h[(size_t)sc * DIM + tid];
            float h3 = g_h[(size_t)sd * DIM + tid];
            acc = fmaf(a0, h0, acc);
            acc = fmaf(a1, h1, acc);
            acc = fmaf(a2, h2, acc);
            acc = fmaf(a3, h3, acc);
        }
        for (; j < len; j++) {
            acc = fmaf(s_alpha[(j << 2) | hd], g_h[(size_t)s_src[j] * DIM + tid], acc);
        }
        __syncthreads();
    }

    // --- bias + residual ---
    float y = acc + __ldg(&bias_gat[tid]) + g_r[(size_t)v * DIM + tid] + __ldg(&b_res[tid]);

    // --- LayerNorm across 256 channels ---
    float sum = y, sq = y * y;
    #pragma unroll
    for (int o = 16; o > 0; o >>= 1) {
        sum += __shfl_xor_sync(0xffffffffu, sum, o);
        sq  += __shfl_xor_sync(0xffffffffu, sq, o);
    }
    int wid = tid >> 5, lane = tid & 31;
    if (lane == 0) { s_s[wid] = sum; s_q[wid] = sq; }
    __syncthreads();
    if (tid == 0) {
        float a = 0.f, b = 0.f;
        #pragma unroll
        for (int w = 0; w < 8; w++) { a += s_s[w]; b += s_q[w]; }
        float mu = a * (1.f / DIM);
        float var = b * (1.f / DIM) - mu * mu;
        s_s[0] = mu;
        s_q[0] = rsqrtf(var + LN_EPS);
    }
    __syncthreads();
    float mu = s_s[0], rstd = s_q[0];
    out[(size_t)v * DIM + tid] = __ldg(&gamma[tid]) * (y - mu) * rstd + __ldg(&beta[tid]);
}

// ---------------- launch ----------------
extern "C" void kernel_launch(void* const* d_in, const int* in_sizes, int n_in,
                              void* d_out, int out_size)
{
    const float* x        = (const float*)d_in[0];
    const void*  ei       = d_in[1];
    const float* W        = (const float*)d_in[2];
    const float* a_src    = (const float*)d_in[3];
    const float* a_dst    = (const float*)d_in[4];
    const float* bias_gat = (const float*)d_in[5];
    const float* W_res    = (const float*)d_in[6];
    const float* b_res    = (const float*)d_in[7];
    const float* gamma    = (const float*)d_in[8];
    const float* beta     = (const float*)d_in[9];
    float* out = (float*)d_out;

    float* d_h; cudaGetSymbolAddress((void**)&d_h, g_h);
    float* d_r; cudaGetSymbolAddress((void**)&d_r, g_r);

    detect_kernel<<<1, 32>>>((const int*)ei);

    dim3 ggrid(2, (NNODES + BM - 1) / BM);
    sgemm_kernel<<<ggrid, 256>>>(x, W,     d_h, NNODES, DIM, DIM);
    sgemm_kernel<<<ggrid, 256>>>(x, W_res, d_r, NNODES, DIM, DIM);

    attn_logits_kernel<<<(NNODES * 32 + 255) / 256, 256>>>(a_src, a_dst);

    init_counts_kernel<<<(NNODES + 255) / 256, 256>>>();
    hist_kernel<<<(NEDGES + 255) / 256, 256>>>(ei);
    scan1_kernel<<<NCHUNK, SCAN_CHUNK>>>();
    scan2_kernel<<<1, 32>>>();
    scan3_kernel<<<(NNODES + 255) / 256, 256>>>();
    scatter_kernel<<<(NEDGES + 255) / 256, 256>>>(ei);

    aggregate_kernel<<<NNODES, 256>>>(bias_gat, b_res, gamma, beta, out);
}

// round 2
// speedup vs baseline: 1.2487x; 1.2487x over previous
#include <cuda_runtime.h>
#include <cuda_fp16.h>
#include <math.h>

#define NNODES 50000
#define DIM    256
#define NH     4
#define NC     64
#define NEDGES 800000
#define EP     (NEDGES + NNODES)   // with self loops
#define NEG_SLOPE 0.2f
#define LN_EPS 1e-5f

#define SCAN_CHUNK 512
#define NCHUNK ((NNODES + SCAN_CHUNK - 1) / SCAN_CHUNK)  // 98

// ---------------- scratch (static device globals; no runtime alloc) ---------
__device__ __half g_hh[(size_t)NNODES * DIM];    // x @ W in fp16 (messages)
__device__ float  g_r[(size_t)NNODES * DIM];     // x @ W_res
__device__ float  g_al_src[NNODES * NH];
__device__ float  g_al_dst[NNODES * NH];
__device__ int    g_count[NNODES];
__device__ int    g_scan[NNODES];
__device__ int    g_bsum[NCHUNK];
__device__ int    g_boff[NCHUNK];
__device__ int    g_rowptr[NNODES + 1];
__device__ int    g_cursor[NNODES];
__device__ int    g_csr_src[EP];
__device__ float  g_csr_e[(size_t)EP * NH];
__device__ int    g_is64;

__device__ __forceinline__ float lrelu(float x) { return x > 0.f ? x : NEG_SLOPE * x; }

__device__ __forceinline__ int edge_at(const void* ei, long long idx) {
    if (g_is64) return (int)((const long long*)ei)[idx];
    return ((const int*)ei)[idx];
}

// ---------------- dtype detection ----------------
__global__ void detect_kernel(const int* __restrict__ ei_words) {
    if (threadIdx.x == 0 && blockIdx.x == 0) {
        int all0 = 1;
        for (int i = 0; i < 128; i++) {
            if (ei_words[2 * i + 1] != 0) { all0 = 0; break; }
        }
        g_is64 = all0;
    }
}

// ---------------- tensor-core GEMM (3xTF32) ----------------
// C[50000 x 512] = x[50000 x 256] @ [W | W_res]  (columns 0..255 -> h fp16 +
// attention logits in epilogue; columns 256..511 -> g_r fp32)
#define BM 128
#define BN 128
#define BKK 16

__device__ __forceinline__ void split_tf32(float f, unsigned& hi, unsigned& lo) {
    unsigned h;
    asm("cvt.rna.tf32.f32 %0, %1;" : "=r"(h) : "f"(f));
    float hf = __uint_as_float(h);
    float lf = f - hf;
    unsigned l;
    asm("cvt.rna.tf32.f32 %0, %1;" : "=r"(l) : "f"(lf));
    hi = h; lo = l;
}

__device__ __forceinline__ void mma_tf32(float* c, const unsigned* a, const unsigned* b) {
    asm volatile(
        "mma.sync.aligned.m16n8k8.row.col.f32.tf32.tf32.f32 "
        "{%0,%1,%2,%3}, {%4,%5,%6,%7}, {%8,%9}, {%0,%1,%2,%3};\n"
        : "+f"(c[0]), "+f"(c[1]), "+f"(c[2]), "+f"(c[3])
        : "r"(a[0]), "r"(a[1]), "r"(a[2]), "r"(a[3]), "r"(b[0]), "r"(b[1]));
}

__global__ __launch_bounds__(256, 1) void mma_gemm_kernel(
    const float* __restrict__ A, const float* __restrict__ W,
    const float* __restrict__ Wres,
    const float* __restrict__ a_src, const float* __restrict__ a_dst)
{
    __shared__ float As[2][BM][BKK + 4];   // [stage][m][k], stride 20
    __shared__ float Bs[2][BKK][BN + 8];   // [stage][k][n], stride 136

    const int tid   = threadIdx.x;
    const int lane  = tid & 31;
    const int warpId = tid >> 5;
    const int warpM = warpId & 3;          // 0..3  -> 32-row slab
    const int warpN = warpId >> 2;         // 0..1  -> 64-col slab (one head)
    const int blockRow = blockIdx.y * BM;
    const bool isH = (blockIdx.x < 2);
    const float* Bmat = isH ? W : Wres;
    const int bcol = (blockIdx.x & 1) * 128;   // col offset within 256-wide matrix

    float acc[2][8][4];
    #pragma unroll
    for (int mt = 0; mt < 2; mt++)
        #pragma unroll
        for (int nt = 0; nt < 8; nt++)
            #pragma unroll
            for (int i = 0; i < 4; i++) acc[mt][nt][i] = 0.f;

    // global load mapping
    const int arow  = tid >> 2;            // 0..63
    const int acol  = (tid & 3) * 4;       // 0,4,8,12
    const int brow  = tid >> 5;            // 0..7
    const int bcol4 = (tid & 31) * 4;      // 0..124

    float4 pa[2], pb[2];

    // prologue: load tile 0
    {
        const int k0 = 0;
        #pragma unroll
        for (int i = 0; i < 2; i++) {
            int r = blockRow + arow + i * 64;
            pa[i] = (r < NNODES) ? *reinterpret_cast<const float4*>(&A[(size_t)r * DIM + k0 + acol])
                                 : make_float4(0.f, 0.f, 0.f, 0.f);
        }
        #pragma unroll
        for (int i = 0; i < 2; i++) {
            int k = k0 + brow + i * 8;
            pb[i] = *reinterpret_cast<const float4*>(&Bmat[(size_t)k * 256 + bcol + bcol4]);
        }
        #pragma unroll
        for (int i = 0; i < 2; i++)
            *reinterpret_cast<float4*>(&As[0][arow + i * 64][acol]) = pa[i];
        #pragma unroll
        for (int i = 0; i < 2; i++)
            *reinterpret_cast<float4*>(&Bs[0][brow + i * 8][bcol4]) = pb[i];
        __syncthreads();
    }

    const int NTILES = DIM / BKK;  // 16
    for (int t = 0; t < NTILES; t++) {
        const int cur = t & 1;
        // prefetch next tile into registers
        if (t + 1 < NTILES) {
            const int k0 = (t + 1) * BKK;
            #pragma unroll
            for (int i = 0; i < 2; i++) {
                int r = blockRow + arow + i * 64;
                pa[i] = (r < NNODES) ? *reinterpret_cast<const float4*>(&A[(size_t)r * DIM + k0 + acol])
                                     : make_float4(0.f, 0.f, 0.f, 0.f);
            }
            #pragma unroll
            for (int i = 0; i < 2; i++) {
                int k = k0 + brow + i * 8;
                pb[i] = *reinterpret_cast<const float4*>(&Bmat[(size_t)k * 256 + bcol + bcol4]);
            }
        }

        // compute on current stage: 2 k-steps of 8
        #pragma unroll
        for (int ks = 0; ks < 2; ks++) {
            const int k0 = ks * 8;
            unsigned ah[2][4], al[2][4];
            #pragma unroll
            for (int mt = 0; mt < 2; mt++) {
                int r = warpM * 32 + mt * 16 + (lane >> 2);
                float e0 = As[cur][r    ][k0 +     (lane & 3)];
                float e1 = As[cur][r + 8][k0 +     (lane & 3)];
                float e2 = As[cur][r    ][k0 + 4 + (lane & 3)];
                float e3 = As[cur][r + 8][k0 + 4 + (lane & 3)];
                split_tf32(e0, ah[mt][0], al[mt][0]);
                split_tf32(e1, ah[mt][1], al[mt][1]);
                split_tf32(e2, ah[mt][2], al[mt][2]);
                split_tf32(e3, ah[mt][3], al[mt][3]);
            }
            unsigned bh[8][2], bl[8][2];
            #pragma unroll
            for (int nt = 0; nt < 8; nt++) {
                int c = warpN * 64 + nt * 8 + (lane >> 2);
                float f0 = Bs[cur][k0 +     (lane & 3)][c];
                float f1 = Bs[cur][k0 + 4 + (lane & 3)][c];
                split_tf32(f0, bh[nt][0], bl[nt][0]);
                split_tf32(f1, bh[nt][1], bl[nt][1]);
            }
            #pragma unroll
            for (int mt = 0; mt < 2; mt++)
                #pragma unroll
                for (int nt = 0; nt < 8; nt++) {
                    mma_tf32(acc[mt][nt], ah[mt], bh[nt]);
                    mma_tf32(acc[mt][nt], al[mt], bh[nt]);
                    mma_tf32(acc[mt][nt], ah[mt], bl[nt]);
                }
        }

        if (t + 1 < NTILES) {
            __syncthreads();   // everyone done computing before anyone... (writes go to other stage, this orders vs stage reuse)
            const int nxt = (t + 1) & 1;
            #pragma unroll
            for (int i = 0; i < 2; i++)
                *reinterpret_cast<float4*>(&As[nxt][arow + i * 64][acol]) = pa[i];
            #pragma unroll
            for (int i = 0; i < 2; i++)
                *reinterpret_cast<float4*>(&Bs[nxt][brow + i * 8][bcol4]) = pb[i];
            __syncthreads();
        }
    }

    // ---------------- epilogue ----------------
    if (isH) {
        float lsrc[2][2] = {{0.f, 0.f}, {0.f, 0.f}};
        float ldst[2][2] = {{0.f, 0.f}, {0.f, 0.f}};
        const int head = (bcol + warpN * 64) >> 6;
        #pragma unroll
        for (int mt = 0; mt < 2; mt++) {
            #pragma unroll
            for (int nt = 0; nt < 8; nt++) {
                int n_loc = warpN * 64 + nt * 8 + 2 * (lane & 3);
                int gcol = bcol + n_loc;              // 0..255
                int row0 = blockRow + warpM * 32 + mt * 16 + (lane >> 2);
                float c0 = acc[mt][nt][0], c1 = acc[mt][nt][1];
                float c2 = acc[mt][nt][2], c3 = acc[mt][nt][3];
                if (row0 < NNODES)
                    *reinterpret_cast<__half2*>(&g_hh[(size_t)row0 * DIM + gcol]) =
                        __floats2half2_rn(c0, c1);
                if (row0 + 8 < NNODES)
                    *reinterpret_cast<__half2*>(&g_hh[(size_t)(row0 + 8) * DIM + gcol]) =
                        __floats2half2_rn(c2, c3);
                int cl = gcol & 63;
                float as0 = __ldg(&a_src[head * 64 + cl]);
                float as1 = __ldg(&a_src[head * 64 + cl + 1]);
                float ad0 = __ldg(&a_dst[head * 64 + cl]);
                float ad1 = __ldg(&a_dst[head * 64 + cl + 1]);
                lsrc[mt][0] = fmaf(c0, as0, fmaf(c1, as1, lsrc[mt][0]));
                lsrc[mt][1] = fmaf(c2, as0, fmaf(c3, as1, lsrc[mt][1]));
                ldst[mt][0] = fmaf(c0, ad0, fmaf(c1, ad1, ldst[mt][0]));
                ldst[mt][1] = fmaf(c2, ad0, fmaf(c3, ad1, ldst[mt][1]));
            }
        }
        #pragma unroll
        for (int mt = 0; mt < 2; mt++)
            #pragma unroll
            for (int rh = 0; rh < 2; rh++) {
                float s = lsrc[mt][rh];
                float d = ldst[mt][rh];
                s += __shfl_xor_sync(0xffffffffu, s, 1);
                s += __shfl_xor_sync(0xffffffffu, s, 2);
                d += __shfl_xor_sync(0xffffffffu, d, 1);
                d += __shfl_xor_sync(0xffffffffu, d, 2);
                int row = blockRow + warpM * 32 + mt * 16 + rh * 8 + (lane >> 2);
                if ((lane & 3) == 0 && row < NNODES) {
                    g_al_src[row * NH + head] = s;
                    g_al_dst[row * NH + head] = d;
                }
            }
    } else {
        #pragma unroll
        for (int mt = 0; mt < 2; mt++) {
            #pragma unroll
            for (int nt = 0; nt < 8; nt++) {
                int n_loc = warpN * 64 + nt * 8 + 2 * (lane & 3);
                int gcol = bcol + n_loc;
                int row0 = blockRow + warpM * 32 + mt * 16 + (lane >> 2);
                if (row0 < NNODES) {
                    float2 v = make_float2(acc[mt][nt][0], acc[mt][nt][1]);
                    *reinterpret_cast<float2*>(&g_r[(size_t)row0 * DIM + gcol]) = v;
                }
                if (row0 + 8 < NNODES) {
                    float2 v = make_float2(acc[mt][nt][2], acc[mt][nt][3]);
                    *reinterpret_cast<float2*>(&g_r[(size_t)(row0 + 8) * DIM + gcol]) = v;
                }
            }
        }
    }
}

// ---------------- CSR build ----------------
__global__ void init_counts_kernel() {
    int i = blockIdx.x * blockDim.x + threadIdx.x;
    if (i < NNODES) g_count[i] = 1;  // self loop
}

__global__ void hist_kernel(const void* __restrict__ ei) {
    int i = blockIdx.x * blockDim.x + threadIdx.x;
    if (i < NEDGES) {
        int d = edge_at(ei, (long long)NEDGES + i);
        atomicAdd(&g_count[d], 1);
    }
}

__global__ __launch_bounds__(SCAN_CHUNK) void scan1_kernel() {
    __shared__ int s[SCAN_CHUNK];
    int i = blockIdx.x * SCAN_CHUNK + threadIdx.x;
    int v = (i < NNODES) ? g_count[i] : 0;
    s[threadIdx.x] = v;
    __syncthreads();
    for (int off = 1; off < SCAN_CHUNK; off <<= 1) {
        int t = s[threadIdx.x];
        int u = (threadIdx.x >= off) ? s[threadIdx.x - off] : 0;
        __syncthreads();
        s[threadIdx.x] = t + u;
        __syncthreads();
    }
    if (i < NNODES) g_scan[i] = s[threadIdx.x];
    if (threadIdx.x == SCAN_CHUNK - 1) g_bsum[blockIdx.x] = s[SCAN_CHUNK - 1];
}

__global__ void scan2_kernel() {
    if (threadIdx.x == 0 && blockIdx.x == 0) {
        int run = 0;
        for (int b = 0; b < NCHUNK; b++) { g_boff[b] = run; run += g_bsum[b]; }
    }
}

__global__ void scan3_kernel() {
    int i = blockIdx.x * blockDim.x + threadIdx.x;
    if (i >= NNODES) return;
    int cnt = g_count[i];
    int incl = g_scan[i] + g_boff[i / SCAN_CHUNK];
    int start = incl - cnt;
    g_rowptr[i] = start;
    g_cursor[i] = start + 1;
    g_csr_src[start] = i;
    float4 es = *reinterpret_cast<const float4*>(&g_al_src[i * NH]);
    float4 ed = *reinterpret_cast<const float4*>(&g_al_dst[i * NH]);
    float4 e = make_float4(lrelu(es.x + ed.x), lrelu(es.y + ed.y),
                           lrelu(es.z + ed.z), lrelu(es.w + ed.w));
    *reinterpret_cast<float4*>(&g_csr_e[(size_t)start * NH]) = e;
    if (i == NNODES - 1) g_rowptr[NNODES] = start + cnt;
}

__global__ void scatter_kernel(const void* __restrict__ ei) {
    int i = blockIdx.x * blockDim.x + threadIdx.x;
    if (i >= NEDGES) return;
    int s = edge_at(ei, i);
    int d = edge_at(ei, (long long)NEDGES + i);
    int pos = atomicAdd(&g_cursor[d], 1);
    g_csr_src[pos] = s;
    float4 es = *reinterpret_cast<const float4*>(&g_al_src[s * NH]);
    float4 ed = *reinterpret_cast<const float4*>(&g_al_dst[d * NH]);
    float4 e = make_float4(lrelu(es.x + ed.x), lrelu(es.y + ed.y),
                           lrelu(es.z + ed.z), lrelu(es.w + ed.w));
    *reinterpret_cast<float4*>(&g_csr_e[(size_t)pos * NH]) = e;
}

// ---------------- fused softmax + aggregate + residual + LayerNorm ----------
#define AGG_CH 128
__global__ __launch_bounds__(256) void aggregate_kernel(
    const float* __restrict__ bias_gat, const float* __restrict__ b_res,
    const float* __restrict__ gamma, const float* __restrict__ beta,
    float* __restrict__ out)
{
    int v = blockIdx.x;
    int tid = threadIdx.x;
    int start = g_rowptr[v];
    int end = g_rowptr[v + 1];
    int deg = end - start;  // >= 1

    __shared__ float s_m[NH], s_inv[NH];
    __shared__ int   s_src[AGG_CH];
    __shared__ float s_alpha[AGG_CH * NH];
    __shared__ float s_s[8], s_q[8];

    if (tid < 32) {
        float m0 = -1e30f, m1 = -1e30f, m2 = -1e30f, m3 = -1e30f;
        for (int j = tid; j < deg; j += 32) {
            float4 e = *reinterpret_cast<const float4*>(&g_csr_e[(size_t)(start + j) * NH]);
            m0 = fmaxf(m0, e.x); m1 = fmaxf(m1, e.y);
            m2 = fmaxf(m2, e.z); m3 = fmaxf(m3, e.w);
        }
        #pragma unroll
        for (int o = 16; o > 0; o >>= 1) {
            m0 = fmaxf(m0, __shfl_xor_sync(0xffffffffu, m0, o));
            m1 = fmaxf(m1, __shfl_xor_sync(0xffffffffu, m1, o));
            m2 = fmaxf(m2, __shfl_xor_sync(0xffffffffu, m2, o));
            m3 = fmaxf(m3, __shfl_xor_sync(0xffffffffu, m3, o));
        }
        float d0 = 0.f, d1 = 0.f, d2 = 0.f, d3 = 0.f;
        for (int j = tid; j < deg; j += 32) {
            float4 e = *reinterpret_cast<const float4*>(&g_csr_e[(size_t)(start + j) * NH]);
            d0 += expf(e.x - m0); d1 += expf(e.y - m1);
            d2 += expf(e.z - m2); d3 += expf(e.w - m3);
        }
        #pragma unroll
        for (int o = 16; o > 0; o >>= 1) {
            d0 += __shfl_xor_sync(0xffffffffu, d0, o);
            d1 += __shfl_xor_sync(0xffffffffu, d1, o);
            d2 += __shfl_xor_sync(0xffffffffu, d2, o);
            d3 += __shfl_xor_sync(0xffffffffu, d3, o);
        }
        if (tid == 0) {
            s_m[0] = m0; s_m[1] = m1; s_m[2] = m2; s_m[3] = m3;
            s_inv[0] = 1.f / (d0 + 1e-16f);
            s_inv[1] = 1.f / (d1 + 1e-16f);
            s_inv[2] = 1.f / (d2 + 1e-16f);
            s_inv[3] = 1.f / (d3 + 1e-16f);
        }
    }
    __syncthreads();

    int hd = tid >> 6;
    float acc = 0.f;

    for (int c0 = 0; c0 < deg; c0 += AGG_CH) {
        int len = min(AGG_CH, deg - c0);
        if (tid < len) s_src[tid] = g_csr_src[start + c0 + tid];
        for (int t = tid; t < len * NH; t += 256) {
            int j = t >> 2, h = t & 3;
            s_alpha[t] = expf(g_csr_e[(size_t)(start + c0 + j) * NH + h] - s_m[h]) * s_inv[h];
        }
        __syncthreads();

        int j = 0;
        for (; j + 4 <= len; j += 4) {
            int sa = s_src[j], sb = s_src[j+1], sc = s_src[j+2], sd = s_src[j+3];
            float a0 = s_alpha[((j    ) << 2) | hd];
            float a1 = s_alpha[((j + 1) << 2) | hd];
            float a2 = s_alpha[((j + 2) << 2) | hd];
            float a3 = s_alpha[((j + 3) << 2) | hd];
            float h0 = __half2float(g_hh[(size_t)sa * DIM + tid]);
            float h1 = __half2float(g_hh[(size_t)sb * DIM + tid]);
            float h2 = __half2float(g_hh[(size_t)sc * DIM + tid]);
            float h3 = __half2float(g_hh[(size_t)sd * DIM + tid]);
            acc = fmaf(a0, h0, acc);
            acc = fmaf(a1, h1, acc);
            acc = fmaf(a2, h2, acc);
            acc = fmaf(a3, h3, acc);
        }
        for (; j < len; j++) {
            acc = fmaf(s_alpha[(j << 2) | hd],
                       __half2float(g_hh[(size_t)s_src[j] * DIM + tid]), acc);
        }
        __syncthreads();
    }

    float y = acc + __ldg(&bias_gat[tid]) + g_r[(size_t)v * DIM + tid] + __ldg(&b_res[tid]);

    float sum = y, sq = y * y;
    #pragma unroll
    for (int o = 16; o > 0; o >>= 1) {
        sum += __shfl_xor_sync(0xffffffffu, sum, o);
        sq  += __shfl_xor_sync(0xffffffffu, sq, o);
    }
    int wid = tid >> 5, lane = tid & 31;
    if (lane == 0) { s_s[wid] = sum; s_q[wid] = sq; }
    __syncthreads();
    if (tid == 0) {
        float a = 0.f, b = 0.f;
        #pragma unroll
        for (int w = 0; w < 8; w++) { a += s_s[w]; b += s_q[w]; }
        float mu = a * (1.f / DIM);
        float var = b * (1.f / DIM) - mu * mu;
        s_s[0] = mu;
        s_q[0] = rsqrtf(var + LN_EPS);
    }
    __syncthreads();
    float mu = s_s[0], rstd = s_q[0];
    out[(size_t)v * DIM + tid] = __ldg(&gamma[tid]) * (y - mu) * rstd + __ldg(&beta[tid]);
}

// ---------------- launch ----------------
extern "C" void kernel_launch(void* const* d_in, const int* in_sizes, int n_in,
                              void* d_out, int out_size)
{
    const float* x        = (const float*)d_in[0];
    const void*  ei       = d_in[1];
    const float* W        = (const float*)d_in[2];
    const float* a_src    = (const float*)d_in[3];
    const float* a_dst    = (const float*)d_in[4];
    const float* bias_gat = (const float*)d_in[5];
    const float* W_res    = (const float*)d_in[6];
    const float* b_res    = (const float*)d_in[7];
    const float* gamma    = (const float*)d_in[8];
    const float* beta     = (const float*)d_in[9];
    float* out = (float*)d_out;

    detect_kernel<<<1, 32>>>((const int*)ei);

    dim3 ggrid(4, (NNODES + BM - 1) / BM);
    mma_gemm_kernel<<<ggrid, 256>>>(x, W, W_res, a_src, a_dst);

    init_counts_kernel<<<(NNODES + 255) / 256, 256>>>();
    hist_kernel<<<(NEDGES + 255) / 256, 256>>>(ei);
    scan1_kernel<<<NCHUNK, SCAN_CHUNK>>>();
    scan2_kernel<<<1, 32>>>();
    scan3_kernel<<<(NNODES + 255) / 256, 256>>>();
    scatter_kernel<<<(NEDGES + 255) / 256, 256>>>(ei);

    aggregate_kernel<<<NNODES, 256>>>(bias_gat, b_res, gamma, beta, out);
}

// round 4
// speedup vs baseline: 2.0231x; 1.6201x over previous
#include <cuda_runtime.h>
#include <cuda_fp16.h>
#include <cuda_bf16.h>
#include <math.h>
#include <stdint.h>

#define NNODES 50000
#define MPAD   50048               // 391 * 128
#define DIM    256
#define NH     4
#define NC     64
#define NEDGES 800000
#define EP     (NEDGES + NNODES)
#define NEG_SLOPE 0.2f
#define LN_EPS 1e-5f

#define SCAN_CHUNK 512
#define NCHUNK ((NNODES + SCAN_CHUNK - 1) / SCAN_CHUNK)

// ---------------- scratch ----------------
__device__ __half         g_hh[(size_t)NNODES * DIM];
__device__ float          g_r[(size_t)NNODES * DIM];
__device__ float          g_al_src[NNODES * NH];
__device__ float          g_al_dst[NNODES * NH];
__device__ __nv_bfloat16  g_xhi[(size_t)MPAD * DIM];
__device__ __nv_bfloat16  g_xlo[(size_t)MPAD * DIM];
__device__ __nv_bfloat16  g_wthi[512 * 256];   // [n][k] = Wcat[k][n]
__device__ __nv_bfloat16  g_wtlo[512 * 256];
__device__ int    g_count[NNODES];
__device__ int    g_scan[NNODES];
__device__ int    g_bsum[NCHUNK];
__device__ int    g_boff[NCHUNK];
__device__ int    g_rowptr[NNODES + 1];
__device__ int    g_cursor[NNODES];
__device__ int    g_csr_src[EP];
__device__ float  g_csr_e[(size_t)EP * NH];
__device__ int    g_is64;

__device__ __forceinline__ float lrelu(float x) { return x > 0.f ? x : NEG_SLOPE * x; }

__device__ __forceinline__ int edge_at(const void* ei, long long idx) {
    if (g_is64) return (int)((const long long*)ei)[idx];
    return ((const int*)ei)[idx];
}

// ---------------- detect ----------------
__global__ void detect_kernel(const int* __restrict__ ei_words) {
    if (threadIdx.x == 0 && blockIdx.x == 0) {
        int all0 = 1;
        for (int i = 0; i < 128; i++)
            if (ei_words[2 * i + 1] != 0) { all0 = 0; break; }
        g_is64 = all0;
    }
}

// ---------------- bf16 hi/lo precompute ----------------
__global__ __launch_bounds__(256) void split_x_kernel(const float* __restrict__ x) {
    long long t = (long long)blockIdx.x * blockDim.x + threadIdx.x;
    long long base = t * 4;
    if (base >= (long long)MPAD * DIM) return;
    long long row = base >> 8;
    __nv_bfloat16 hi[4], lo[4];
    if (row < NNODES) {
        float4 v = *reinterpret_cast<const float4*>(&x[base]);
        float f[4] = {v.x, v.y, v.z, v.w};
        #pragma unroll
        for (int i = 0; i < 4; i++) {
            hi[i] = __float2bfloat16_rn(f[i]);
            lo[i] = __float2bfloat16_rn(f[i] - __bfloat162float(hi[i]));
        }
    } else {
        #pragma unroll
        for (int i = 0; i < 4; i++) { hi[i] = __float2bfloat16_rn(0.f); lo[i] = hi[i]; }
    }
    *reinterpret_cast<uint2*>(&g_xhi[base]) = *reinterpret_cast<uint2*>(hi);
    *reinterpret_cast<uint2*>(&g_xlo[base]) = *reinterpret_cast<uint2*>(lo);
}

__global__ __launch_bounds__(256) void split_w_kernel(const float* __restrict__ W,
                                                      const float* __restrict__ Wres) {
    int idx = blockIdx.x * blockDim.x + threadIdx.x;   // over 512*256
    if (idx >= 512 * 256) return;
    int n = idx >> 8, k = idx & 255;
    float v = (n < 256) ? W[k * 256 + n] : Wres[k * 256 + (n - 256)];
    __nv_bfloat16 hi = __float2bfloat16_rn(v);
    __nv_bfloat16 lo = __float2bfloat16_rn(v - __bfloat162float(hi));
    g_wthi[idx] = hi;
    g_wtlo[idx] = lo;
}

// ---------------- bf16 mma.sync GEMM ----------------
// grid (4, 391): x-blocks 0,1 -> h (+logits), 2,3 -> r. 128 rows x 128 cols / CTA.
#define TS 40                         // smem stride in bf16 (80 bytes): conflict-free
#define TILE_BYTES (128 * TS * 2)     // 10240
#define STAGE_BYTES (4 * TILE_BYTES)  // 40960

__device__ __forceinline__ uint32_t smem_u32(const void* p) {
    uint32_t a;
    asm("{ .reg .u64 t; cvta.to.shared.u64 t, %1; cvt.u32.u64 %0, t; }" : "=r"(a) : "l"(p));
    return a;
}
__device__ __forceinline__ void cp16(uint32_t s, const void* g) {
    asm volatile("cp.async.cg.shared.global [%0], [%1], 16;" :: "r"(s), "l"(g));
}
#define CP_COMMIT() asm volatile("cp.async.commit_group;" ::: "memory")
#define CP_WAIT(n)  asm volatile("cp.async.wait_group %0;" :: "n"(n) : "memory")

__device__ __forceinline__ void mma_bf16(float* c, const uint32_t* a, const uint32_t* b) {
    asm volatile(
        "mma.sync.aligned.m16n8k16.row.col.f32.bf16.bf16.f32 "
        "{%0,%1,%2,%3}, {%4,%5,%6,%7}, {%8,%9}, {%0,%1,%2,%3};\n"
        : "+f"(c[0]), "+f"(c[1]), "+f"(c[2]), "+f"(c[3])
        : "r"(a[0]), "r"(a[1]), "r"(a[2]), "r"(a[3]), "r"(b[0]), "r"(b[1]));
}

__global__ __launch_bounds__(256, 1) void bf16_gemm_kernel(
    const float* __restrict__ a_src, const float* __restrict__ a_dst)
{
    extern __shared__ char smem[];
    const uint32_t sbase = smem_u32(smem);
    const int tid = threadIdx.x;
    const int lane = tid & 31;
    const int warpId = tid >> 5;
    const int warpM = warpId & 3;          // 32-row slab
    const int warpN = warpId >> 2;         // 64-col slab
    const int blockRow = blockIdx.y * 128;
    const int cb = blockIdx.x;             // 0..3
    const bool isH = (cb < 2);
    const int bcol = cb * 128;

    const char* ah = reinterpret_cast<const char*>(g_xhi) + (size_t)blockRow * 512;
    const char* al = reinterpret_cast<const char*>(g_xlo) + (size_t)blockRow * 512;
    const char* wh = reinterpret_cast<const char*>(g_wthi) + (size_t)bcol * 512;
    const char* wl = reinterpret_cast<const char*>(g_wtlo) + (size_t)bcol * 512;

    float acc[2][8][4];
    #pragma unroll
    for (int mt = 0; mt < 2; mt++)
        #pragma unroll
        for (int nt = 0; nt < 8; nt++)
            #pragma unroll
            for (int i = 0; i < 4; i++) acc[mt][nt][i] = 0.f;

    // stage loader: chunk c covers k bytes [c*64, c*64+64) of each 512B row
    auto load_stage = [&](int s, int c) {
        uint32_t stg = sbase + s * STAGE_BYTES;
        const int kb = c * 64;
        #pragma unroll
        for (int j = 0; j < 2; j++) {
            int idx = tid + j * 256;       // 0..511
            int row = idx >> 2, seg = idx & 3;
            uint32_t so = (uint32_t)(row * 80 + seg * 16);
            size_t go = (size_t)row * 512 + kb + seg * 16;
            cp16(stg + so,                  ah + go);
            cp16(stg + TILE_BYTES + so,     al + go);
            cp16(stg + 2 * TILE_BYTES + so, wh + go);
            cp16(stg + 3 * TILE_BYTES + so, wl + go);
        }
    };

    load_stage(0, 0);
    CP_COMMIT();

    for (int c = 0; c < 8; c++) {
        if (c + 1 < 8) {
            load_stage((c + 1) & 1, c + 1);
            CP_COMMIT();
            CP_WAIT(1);
        } else {
            CP_WAIT(0);
        }
        __syncthreads();

        const char* stg = smem + (size_t)(c & 1) * STAGE_BYTES;
        const char* As_h = stg;
        const char* As_l = stg + TILE_BYTES;
        const char* Bs_h = stg + 2 * TILE_BYTES;
        const char* Bs_l = stg + 3 * TILE_BYTES;

        #pragma unroll
        for (int ks = 0; ks < 2; ks++) {
            const int kbyte = ks * 32;     // k16 step within 32-k chunk
            uint32_t Ah[2][4], Al[2][4];
            #pragma unroll
            for (int mt = 0; mt < 2; mt++) {
                int r = warpM * 32 + mt * 16 + (lane >> 2);
                int boff = r * 80 + kbyte + (lane & 3) * 4;
                Ah[mt][0] = *reinterpret_cast<const uint32_t*>(As_h + boff);
                Ah[mt][1] = *reinterpret_cast<const uint32_t*>(As_h + boff + 8 * 80);
                Ah[mt][2] = *reinterpret_cast<const uint32_t*>(As_h + boff + 16);
                Ah[mt][3] = *reinterpret_cast<const uint32_t*>(As_h + boff + 8 * 80 + 16);
                Al[mt][0] = *reinterpret_cast<const uint32_t*>(As_l + boff);
                Al[mt][1] = *reinterpret_cast<const uint32_t*>(As_l + boff + 8 * 80);
                Al[mt][2] = *reinterpret_cast<const uint32_t*>(As_l + boff + 16);
                Al[mt][3] = *reinterpret_cast<const uint32_t*>(As_l + boff + 8 * 80 + 16);
            }
            uint32_t Bh[8][2], Bl[8][2];
            #pragma unroll
            for (int nt = 0; nt < 8; nt++) {
                int n = warpN * 64 + nt * 8 + (lane >> 2);
                int boff = n * 80 + kbyte + (lane & 3) * 4;
                Bh[nt][0] = *reinterpret_cast<const uint32_t*>(Bs_h + boff);
                Bh[nt][1] = *reinterpret_cast<const uint32_t*>(Bs_h + boff + 16);
                Bl[nt][0] = *reinterpret_cast<const uint32_t*>(Bs_l + boff);
                Bl[nt][1] = *reinterpret_cast<const uint32_t*>(Bs_l + boff + 16);
            }
            #pragma unroll
            for (int mt = 0; mt < 2; mt++)
                #pragma unroll
                for (int nt = 0; nt < 8; nt++) {
                    mma_bf16(acc[mt][nt], Ah[mt], Bh[nt]);
                    mma_bf16(acc[mt][nt], Al[mt], Bh[nt]);
                    mma_bf16(acc[mt][nt], Ah[mt], Bl[nt]);
                }
        }
        __syncthreads();
    }

    // ---------------- epilogue (same layout as R2, proven) ----------------
    if (isH) {
        float lsrc[2][2] = {{0.f, 0.f}, {0.f, 0.f}};
        float ldst[2][2] = {{0.f, 0.f}, {0.f, 0.f}};
        const int head = (bcol + warpN * 64) >> 6;
        #pragma unroll
        for (int mt = 0; mt < 2; mt++) {
            #pragma unroll
            for (int nt = 0; nt < 8; nt++) {
                int n_loc = warpN * 64 + nt * 8 + 2 * (lane & 3);
                int gcol = bcol + n_loc;
                int row0 = blockRow + warpM * 32 + mt * 16 + (lane >> 2);
                float c0 = acc[mt][nt][0], c1 = acc[mt][nt][1];
                float c2 = acc[mt][nt][2], c3 = acc[mt][nt][3];
                if (row0 < NNODES)
                    *reinterpret_cast<__half2*>(&g_hh[(size_t)row0 * DIM + gcol]) =
                        __floats2half2_rn(c0, c1);
                if (row0 + 8 < NNODES)
                    *reinterpret_cast<__half2*>(&g_hh[(size_t)(row0 + 8) * DIM + gcol]) =
                        __floats2half2_rn(c2, c3);
                int cl = gcol & 63;
                float as0 = __ldg(&a_src[head * 64 + cl]);
                float as1 = __ldg(&a_src[head * 64 + cl + 1]);
                float ad0 = __ldg(&a_dst[head * 64 + cl]);
                float ad1 = __ldg(&a_dst[head * 64 + cl + 1]);
                lsrc[mt][0] = fmaf(c0, as0, fmaf(c1, as1, lsrc[mt][0]));
                lsrc[mt][1] = fmaf(c2, as0, fmaf(c3, as1, lsrc[mt][1]));
                ldst[mt][0] = fmaf(c0, ad0, fmaf(c1, ad1, ldst[mt][0]));
                ldst[mt][1] = fmaf(c2, ad0, fmaf(c3, ad1, ldst[mt][1]));
            }
        }
        #pragma unroll
        for (int mt = 0; mt < 2; mt++)
            #pragma unroll
            for (int rh = 0; rh < 2; rh++) {
                float s = lsrc[mt][rh];
                float d = ldst[mt][rh];
                s += __shfl_xor_sync(0xffffffffu, s, 1);
                s += __shfl_xor_sync(0xffffffffu, s, 2);
                d += __shfl_xor_sync(0xffffffffu, d, 1);
                d += __shfl_xor_sync(0xffffffffu, d, 2);
                int row = blockRow + warpM * 32 + mt * 16 + rh * 8 + (lane >> 2);
                if ((lane & 3) == 0 && row < NNODES) {
                    g_al_src[row * NH + head] = s;
                    g_al_dst[row * NH + head] = d;
                }
            }
    } else {
        #pragma unroll
        for (int mt = 0; mt < 2; mt++) {
            #pragma unroll
            for (int nt = 0; nt < 8; nt++) {
                int n_loc = warpN * 64 + nt * 8 + 2 * (lane & 3);
                int gcol = (bcol - 256) + n_loc;
                int row0 = blockRow + warpM * 32 + mt * 16 + (lane >> 2);
                if (row0 < NNODES) {
                    float2 v = make_float2(acc[mt][nt][0], acc[mt][nt][1]);
                    *reinterpret_cast<float2*>(&g_r[(size_t)row0 * DIM + gcol]) = v;
                }
                if (row0 + 8 < NNODES) {
                    float2 v = make_float2(acc[mt][nt][2], acc[mt][nt][3]);
                    *reinterpret_cast<float2*>(&g_r[(size_t)(row0 + 8) * DIM + gcol]) = v;
                }
            }
        }
    }
}

// ---------------- CSR build ----------------
__global__ void init_counts_kernel() {
    int i = blockIdx.x * blockDim.x + threadIdx.x;
    if (i < NNODES) g_count[i] = 1;
}

__global__ void hist_kernel(const void* __restrict__ ei) {
    int i = blockIdx.x * blockDim.x + threadIdx.x;
    if (i < NEDGES) {
        int d = edge_at(ei, (long long)NEDGES + i);
        atomicAdd(&g_count[d], 1);
    }
}

__global__ __launch_bounds__(SCAN_CHUNK) void scan1_kernel() {
    __shared__ int s[SCAN_CHUNK];
    int i = blockIdx.x * SCAN_CHUNK + threadIdx.x;
    int v = (i < NNODES) ? g_count[i] : 0;
    s[threadIdx.x] = v;
    __syncthreads();
    for (int off = 1; off < SCAN_CHUNK; off <<= 1) {
        int t = s[threadIdx.x];
        int u = (threadIdx.x >= off) ? s[threadIdx.x - off] : 0;
        __syncthreads();
        s[threadIdx.x] = t + u;
        __syncthreads();
    }
    if (i < NNODES) g_scan[i] = s[threadIdx.x];
    if (threadIdx.x == SCAN_CHUNK - 1) g_bsum[blockIdx.x] = s[SCAN_CHUNK - 1];
}

__global__ void scan2_kernel() {
    if (threadIdx.x == 0 && blockIdx.x == 0) {
        int run = 0;
        for (int b = 0; b < NCHUNK; b++) { g_boff[b] = run; run += g_bsum[b]; }
    }
}

__global__ void scan3_kernel() {
    int i = blockIdx.x * blockDim.x + threadIdx.x;
    if (i >= NNODES) return;
    int cnt = g_count[i];
    int incl = g_scan[i] + g_boff[i / SCAN_CHUNK];
    int start = incl - cnt;
    g_rowptr[i] = start;
    g_cursor[i] = start + 1;
    g_csr_src[start] = i;
    float4 es = *reinterpret_cast<const float4*>(&g_al_src[i * NH]);
    float4 ed = *reinterpret_cast<const float4*>(&g_al_dst[i * NH]);
    float4 e = make_float4(lrelu(es.x + ed.x), lrelu(es.y + ed.y),
                           lrelu(es.z + ed.z), lrelu(es.w + ed.w));
    *reinterpret_cast<float4*>(&g_csr_e[(size_t)start * NH]) = e;
    if (i == NNODES - 1) g_rowptr[NNODES] = start + cnt;
}

__global__ void scatter_kernel(const void* __restrict__ ei) {
    int i = blockIdx.x * blockDim.x + threadIdx.x;
    if (i >= NEDGES) return;
    int s = edge_at(ei, i);
    int d = edge_at(ei, (long long)NEDGES + i);
    int pos = atomicAdd(&g_cursor[d], 1);
    g_csr_src[pos] = s;
    float4 es = *reinterpret_cast<const float4*>(&g_al_src[s * NH]);
    float4 ed = *reinterpret_cast<const float4*>(&g_al_dst[d * NH]);
    float4 e = make_float4(lrelu(es.x + ed.x), lrelu(es.y + ed.y),
                           lrelu(es.z + ed.z), lrelu(es.w + ed.w));
    *reinterpret_cast<float4*>(&g_csr_e[(size_t)pos * NH]) = e;
}

// ---------------- fused softmax + aggregate + residual + LayerNorm ----------
// 128 threads per node; each thread owns 2 channels (half2).
#define AGG_CH 128
__global__ __launch_bounds__(128) void aggregate_kernel(
    const float* __restrict__ bias_gat, const float* __restrict__ b_res,
    const float* __restrict__ gamma, const float* __restrict__ beta,
    float* __restrict__ out)
{
    int v = blockIdx.x;
    int tid = threadIdx.x;
    int start = g_rowptr[v];
    int deg = g_rowptr[v + 1] - start;

    __shared__ float s_m[NH], s_inv[NH];
    __shared__ int   s_src[AGG_CH];
    __shared__ float s_alpha[AGG_CH * NH];
    __shared__ float s_s[4], s_q[4];

    if (tid < 32) {
        float m0 = -1e30f, m1 = -1e30f, m2 = -1e30f, m3 = -1e30f;
        for (int j = tid; j < deg; j += 32) {
            float4 e = *reinterpret_cast<const float4*>(&g_csr_e[(size_t)(start + j) * NH]);
            m0 = fmaxf(m0, e.x); m1 = fmaxf(m1, e.y);
            m2 = fmaxf(m2, e.z); m3 = fmaxf(m3, e.w);
        }
        #pragma unroll
        for (int o = 16; o > 0; o >>= 1) {
            m0 = fmaxf(m0, __shfl_xor_sync(0xffffffffu, m0, o));
            m1 = fmaxf(m1, __shfl_xor_sync(0xffffffffu, m1, o));
            m2 = fmaxf(m2, __shfl_xor_sync(0xffffffffu, m2, o));
            m3 = fmaxf(m3, __shfl_xor_sync(0xffffffffu, m3, o));
        }
        float d0 = 0.f, d1 = 0.f, d2 = 0.f, d3 = 0.f;
        for (int j = tid; j < deg; j += 32) {
            float4 e = *reinterpret_cast<const float4*>(&g_csr_e[(size_t)(start + j) * NH]);
            d0 += expf(e.x - m0); d1 += expf(e.y - m1);
            d2 += expf(e.z - m2); d3 += expf(e.w - m3);
        }
        #pragma unroll
        for (int o = 16; o > 0; o >>= 1) {
            d0 += __shfl_xor_sync(0xffffffffu, d0, o);
            d1 += __shfl_xor_sync(0xffffffffu, d1, o);
            d2 += __shfl_xor_sync(0xffffffffu, d2, o);
            d3 += __shfl_xor_sync(0xffffffffu, d3, o);
        }
        if (tid == 0) {
            s_m[0] = m0; s_m[1] = m1; s_m[2] = m2; s_m[3] = m3;
            s_inv[0] = 1.f / (d0 + 1e-16f);
            s_inv[1] = 1.f / (d1 + 1e-16f);
            s_inv[2] = 1.f / (d2 + 1e-16f);
            s_inv[3] = 1.f / (d3 + 1e-16f);
        }
    }
    __syncthreads();

    const int hd = tid >> 5;
    float2 acc = make_float2(0.f, 0.f);
    const __half2* hh2 = reinterpret_cast<const __half2*>(g_hh);

    for (int c0 = 0; c0 < deg; c0 += AGG_CH) {
        int len = min(AGG_CH, deg - c0);
        if (tid < len) s_src[tid] = g_csr_src[start + c0 + tid];
        for (int t = tid; t < len * NH; t += 128) {
            int j = t >> 2, h = t & 3;
            s_alpha[t] = expf(g_csr_e[(size_t)(start + c0 + j) * NH + h] - s_m[h]) * s_inv[h];
        }
        __syncthreads();

        int j = 0;
        for (; j + 4 <= len; j += 4) {
            int sa = s_src[j], sb = s_src[j+1], sc = s_src[j+2], sd = s_src[j+3];
            float a0 = s_alpha[((j    ) << 2) | hd];
            float a1 = s_alpha[((j + 1) << 2) | hd];
            float a2 = s_alpha[((j + 2) << 2) | hd];
            float a3 = s_alpha[((j + 3) << 2) | hd];
            float2 h0 = __half22float2(hh2[(size_t)sa * 128 + tid]);
            float2 h1 = __half22float2(hh2[(size_t)sb * 128 + tid]);
            float2 h2 = __half22float2(hh2[(size_t)sc * 128 + tid]);
            float2 h3 = __half22float2(hh2[(size_t)sd * 128 + tid]);
            acc.x = fmaf(a0, h0.x, acc.x); acc.y = fmaf(a0, h0.y, acc.y);
            acc.x = fmaf(a1, h1.x, acc.x); acc.y = fmaf(a1, h1.y, acc.y);
            acc.x = fmaf(a2, h2.x, acc.x); acc.y = fmaf(a2, h2.y, acc.y);
            acc.x = fmaf(a3, h3.x, acc.x); acc.y = fmaf(a3, h3.y, acc.y);
        }
        for (; j < len; j++) {
            float a = s_alpha[(j << 2) | hd];
            float2 hv = __half22float2(hh2[(size_t)s_src[j] * 128 + tid]);
            acc.x = fmaf(a, hv.x, acc.x);
            acc.y = fmaf(a, hv.y, acc.y);
        }
        __syncthreads();
    }

    float2 bg = *reinterpret_cast<const float2*>(&bias_gat[2 * tid]);
    float2 br = *reinterpret_cast<const float2*>(&b_res[2 * tid]);
    float2 rr = *reinterpret_cast<const float2*>(&g_r[(size_t)v * DIM + 2 * tid]);
    float y0 = acc.x + bg.x + rr.x + br.x;
    float y1 = acc.y + bg.y + rr.y + br.y;

    float sum = y0 + y1, sq = y0 * y0 + y1 * y1;
    #pragma unroll
    for (int o = 16; o > 0; o >>= 1) {
        sum += __shfl_xor_sync(0xffffffffu, sum, o);
        sq  += __shfl_xor_sync(0xffffffffu, sq, o);
    }
    int wid = tid >> 5, lane = tid & 31;
    if (lane == 0) { s_s[wid] = sum; s_q[wid] = sq; }
    __syncthreads();
    if (tid == 0) {
        float a = s_s[0] + s_s[1] + s_s[2] + s_s[3];
        float b = s_q[0] + s_q[1] + s_q[2] + s_q[3];
        float mu = a * (1.f / DIM);
        float var = b * (1.f / DIM) - mu * mu;
        s_s[0] = mu;
        s_q[0] = rsqrtf(var + LN_EPS);
    }
    __syncthreads();
    float mu = s_s[0], rstd = s_q[0];
    float2 gm = *reinterpret_cast<const float2*>(&gamma[2 * tid]);
    float2 bt = *reinterpret_cast<const float2*>(&beta[2 * tid]);
    float2 o2 = make_float2(gm.x * (y0 - mu) * rstd + bt.x,
                            gm.y * (y1 - mu) * rstd + bt.y);
    *reinterpret_cast<float2*>(&out[(size_t)v * DIM + 2 * tid]) = o2;
}

// ---------------- launch ----------------
extern "C" void kernel_launch(void* const* d_in, const int* in_sizes, int n_in,
                              void* d_out, int out_size)
{
    const float* x        = (const float*)d_in[0];
    const void*  ei       = d_in[1];
    const float* W        = (const float*)d_in[2];
    const float* a_src    = (const float*)d_in[3];
    const float* a_dst    = (const float*)d_in[4];
    const float* bias_gat = (const float*)d_in[5];
    const float* W_res    = (const float*)d_in[6];
    const float* b_res    = (const float*)d_in[7];
    const float* gamma    = (const float*)d_in[8];
    const float* beta     = (const float*)d_in[9];
    float* out = (float*)d_out;

    static int smem_set = 0;
    const int SMEM = 2 * STAGE_BYTES;  // 81920
    if (!smem_set) {
        cudaFuncSetAttribute(bf16_gemm_kernel, cudaFuncAttributeMaxDynamicSharedMemorySize, SMEM);
        smem_set = 1;
    }

    detect_kernel<<<1, 32>>>((const int*)ei);
    split_x_kernel<<<((long long)MPAD * DIM / 4 + 255) / 256, 256>>>(x);
    split_w_kernel<<<(512 * 256 + 255) / 256, 256>>>(W, W_res);

    dim3 ggrid(4, MPAD / 128);
    bf16_gemm_kernel<<<ggrid, 256, SMEM>>>(a_src, a_dst);

    init_counts_kernel<<<(NNODES + 255) / 256, 256>>>();
    hist_kernel<<<(NEDGES + 255) / 256, 256>>>(ei);
    scan1_kernel<<<NCHUNK, SCAN_CHUNK>>>();
    scan2_kernel<<<1, 32>>>();
    scan3_kernel<<<(NNODES + 255) / 256, 256>>>();
    scatter_kernel<<<(NEDGES + 255) / 256, 256>>>(ei);

    aggregate_kernel<<<NNODES, 128>>>(bias_gat, b_res, gamma, beta, out);
}

// round 5
// speedup vs baseline: 2.2099x; 1.0923x over previous
#include <cuda_runtime.h>
#include <cuda_fp16.h>
#include <cuda_bf16.h>
#include <math.h>
#include <stdint.h>

#define NNODES 50000
#define MPAD   50048               // 391 * 128
#define DIM    256
#define NH     4
#define NC     64
#define NEDGES 800000
#define EP     (NEDGES + NNODES)
#define NEG_SLOPE 0.2f
#define LN_EPS 1e-5f

#define SCAN_CHUNK 512
#define NCHUNK ((NNODES + SCAN_CHUNK - 1) / SCAN_CHUNK)

// ---------------- scratch ----------------
__device__ __half         g_hh[(size_t)NNODES * DIM];
__device__ float          g_r[(size_t)NNODES * DIM];
__device__ float          g_al_src[NNODES * NH];
__device__ float          g_al_dst[NNODES * NH];
__device__ __nv_bfloat16  g_xhi[(size_t)MPAD * DIM];
__device__ __nv_bfloat16  g_xlo[(size_t)MPAD * DIM];
__device__ __nv_bfloat16  g_wthi[512 * 256];   // [n][k] = Wcat[k][n]
__device__ __nv_bfloat16  g_wtlo[512 * 256];
__device__ int    g_count[NNODES];
__device__ int    g_scan[NNODES];
__device__ int    g_bsum[NCHUNK];
__device__ int    g_boff[NCHUNK];
__device__ int    g_rowptr[NNODES + 1];
__device__ int    g_cursor[NNODES];
__device__ int    g_csr_src[EP];
__device__ float  g_csr_e[(size_t)EP * NH];
__device__ int    g_is64;

__device__ __forceinline__ float lrelu(float x) { return x > 0.f ? x : NEG_SLOPE * x; }

__device__ __forceinline__ int edge_at(const void* ei, long long idx) {
    if (g_is64) return (int)((const long long*)ei)[idx];
    return ((const int*)ei)[idx];
}

// ---------------- detect + init counts ----------------
__global__ void detect_init_kernel(const int* __restrict__ ei_words) {
    int i = blockIdx.x * blockDim.x + threadIdx.x;
    if (i < NNODES) g_count[i] = 1;   // self loop
    if (i == 0) {
        int all0 = 1;
        for (int k = 0; k < 128; k++)
            if (ei_words[2 * k + 1] != 0) { all0 = 0; break; }
        g_is64 = all0;
    }
}

// ---------------- bf16 hi/lo precompute ----------------
__global__ __launch_bounds__(256) void split_x_kernel(const float* __restrict__ x) {
    long long t = (long long)blockIdx.x * blockDim.x + threadIdx.x;
    long long base = t * 4;
    if (base >= (long long)MPAD * DIM) return;
    long long row = base >> 8;
    __nv_bfloat16 hi[4], lo[4];
    if (row < NNODES) {
        float4 v = *reinterpret_cast<const float4*>(&x[base]);
        float f[4] = {v.x, v.y, v.z, v.w};
        #pragma unroll
        for (int i = 0; i < 4; i++) {
            hi[i] = __float2bfloat16_rn(f[i]);
            lo[i] = __float2bfloat16_rn(f[i] - __bfloat162float(hi[i]));
        }
    } else {
        #pragma unroll
        for (int i = 0; i < 4; i++) { hi[i] = __float2bfloat16_rn(0.f); lo[i] = hi[i]; }
    }
    *reinterpret_cast<uint2*>(&g_xhi[base]) = *reinterpret_cast<uint2*>(hi);
    *reinterpret_cast<uint2*>(&g_xlo[base]) = *reinterpret_cast<uint2*>(lo);
}

__global__ __launch_bounds__(256) void split_w_kernel(const float* __restrict__ W,
                                                      const float* __restrict__ Wres) {
    int idx = blockIdx.x * blockDim.x + threadIdx.x;
    if (idx >= 512 * 256) return;
    int n = idx >> 8, k = idx & 255;
    float v = (n < 256) ? W[k * 256 + n] : Wres[k * 256 + (n - 256)];
    __nv_bfloat16 hi = __float2bfloat16_rn(v);
    __nv_bfloat16 lo = __float2bfloat16_rn(v - __bfloat162float(hi));
    g_wthi[idx] = hi;
    g_wtlo[idx] = lo;
}

// ---------------- bf16 mma.sync GEMM (ldmatrix) ----------------
#define TS 40                         // smem row stride in bf16 (80 bytes)
#define TILE_BYTES (128 * TS * 2)     // 10240
#define STAGE_BYTES (4 * TILE_BYTES)  // 40960

__device__ __forceinline__ uint32_t smem_u32(const void* p) {
    uint32_t a;
    asm("{ .reg .u64 t; cvta.to.shared.u64 t, %1; cvt.u32.u64 %0, t; }" : "=r"(a) : "l"(p));
    return a;
}
__device__ __forceinline__ void cp16(uint32_t s, const void* g) {
    asm volatile("cp.async.cg.shared.global [%0], [%1], 16;" :: "r"(s), "l"(g));
}
#define CP_COMMIT() asm volatile("cp.async.commit_group;" ::: "memory")
#define CP_WAIT(n)  asm volatile("cp.async.wait_group %0;" :: "n"(n) : "memory")

__device__ __forceinline__ void ldsm4(uint32_t addr, uint32_t* d) {
    asm volatile("ldmatrix.sync.aligned.m8n8.x4.shared.b16 {%0,%1,%2,%3}, [%4];"
        : "=r"(d[0]), "=r"(d[1]), "=r"(d[2]), "=r"(d[3]) : "r"(addr));
}

__device__ __forceinline__ void mma_bf16(float* c, const uint32_t* a, const uint32_t* b) {
    asm volatile(
        "mma.sync.aligned.m16n8k16.row.col.f32.bf16.bf16.f32 "
        "{%0,%1,%2,%3}, {%4,%5,%6,%7}, {%8,%9}, {%0,%1,%2,%3};\n"
        : "+f"(c[0]), "+f"(c[1]), "+f"(c[2]), "+f"(c[3])
        : "r"(a[0]), "r"(a[1]), "r"(a[2]), "r"(a[3]), "r"(b[0]), "r"(b[1]));
}

__global__ __launch_bounds__(256, 2) void bf16_gemm_kernel(
    const float* __restrict__ a_src, const float* __restrict__ a_dst)
{
    extern __shared__ char smem[];
    const uint32_t sbase = smem_u32(smem);
    const int tid = threadIdx.x;
    const int lane = tid & 31;
    const int warpId = tid >> 5;
    const int warpM = warpId & 3;          // 32-row slab
    const int warpN = warpId >> 2;         // 64-col slab
    const int blockRow = blockIdx.y * 128;
    const int cb = blockIdx.x;             // 0..3
    const bool isH = (cb < 2);
    const int bcol = cb * 128;

    const char* ah = reinterpret_cast<const char*>(g_xhi) + (size_t)blockRow * 512;
    const char* al = reinterpret_cast<const char*>(g_xlo) + (size_t)blockRow * 512;
    const char* wh = reinterpret_cast<const char*>(g_wthi) + (size_t)bcol * 512;
    const char* wl = reinterpret_cast<const char*>(g_wtlo) + (size_t)bcol * 512;

    float acc[2][8][4];
    #pragma unroll
    for (int mt = 0; mt < 2; mt++)
        #pragma unroll
        for (int nt = 0; nt < 8; nt++)
            #pragma unroll
            for (int i = 0; i < 4; i++) acc[mt][nt][i] = 0.f;

    // ldmatrix lane addressing
    const int q = lane >> 3, r = lane & 7;
    // A frag: q0: m+r,k0 | q1: m+8+r,k0 | q2: m+r,k16 | q3: m+8+r,k16
    const uint32_t aOff = (uint32_t)((warpM * 32 + (q & 1) * 8 + r) * 80 + (q >> 1) * 16);
    // B frag-pair: q0: n+r,k0 | q1: n+r,k16 | q2: n+8+r,k0 | q3: n+8+r,k16
    const uint32_t bOff = (uint32_t)((warpN * 64 + (q >> 1) * 8 + r) * 80 + (q & 1) * 16);

    auto load_stage = [&](int s, int c) {
        uint32_t stg = sbase + s * STAGE_BYTES;
        const int kb = c * 64;
        #pragma unroll
        for (int j = 0; j < 2; j++) {
            int idx = tid + j * 256;
            int row = idx >> 2, seg = idx & 3;
            uint32_t so = (uint32_t)(row * 80 + seg * 16);
            size_t go = (size_t)row * 512 + kb + seg * 16;
            cp16(stg + so,                  ah + go);
            cp16(stg + TILE_BYTES + so,     al + go);
            cp16(stg + 2 * TILE_BYTES + so, wh + go);
            cp16(stg + 3 * TILE_BYTES + so, wl + go);
        }
    };

    load_stage(0, 0);
    CP_COMMIT();

    for (int c = 0; c < 8; c++) {
        if (c + 1 < 8) {
            load_stage((c + 1) & 1, c + 1);
            CP_COMMIT();
            CP_WAIT(1);
        } else {
            CP_WAIT(0);
        }
        __syncthreads();

        const uint32_t stg = sbase + (uint32_t)(c & 1) * STAGE_BYTES;
        const uint32_t As_h = stg;
        const uint32_t As_l = stg + TILE_BYTES;
        const uint32_t Bs_h = stg + 2 * TILE_BYTES;
        const uint32_t Bs_l = stg + 3 * TILE_BYTES;

        #pragma unroll
        for (int ks = 0; ks < 2; ks++) {
            const uint32_t kbyte = ks * 32;
            uint32_t Ah[2][4], Al[2][4];
            #pragma unroll
            for (int mt = 0; mt < 2; mt++) {
                ldsm4(As_h + aOff + mt * (16 * 80) + kbyte, Ah[mt]);
                ldsm4(As_l + aOff + mt * (16 * 80) + kbyte, Al[mt]);
            }
            #pragma unroll
            for (int ntp = 0; ntp < 4; ntp++) {
                uint32_t Bh[4], Bl[4];
                ldsm4(Bs_h + bOff + ntp * (16 * 80) + kbyte, Bh);
                ldsm4(Bs_l + bOff + ntp * (16 * 80) + kbyte, Bl);
                #pragma unroll
                for (int mt = 0; mt < 2; mt++) {
                    mma_bf16(acc[mt][ntp * 2],     Ah[mt], Bh);
                    mma_bf16(acc[mt][ntp * 2],     Al[mt], Bh);
                    mma_bf16(acc[mt][ntp * 2],     Ah[mt], Bl);
                    mma_bf16(acc[mt][ntp * 2 + 1], Ah[mt], Bh + 2);
                    mma_bf16(acc[mt][ntp * 2 + 1], Al[mt], Bh + 2);
                    mma_bf16(acc[mt][ntp * 2 + 1], Ah[mt], Bl + 2);
                }
            }
        }
        __syncthreads();
    }

    // ---------------- epilogue ----------------
    if (isH) {
        float lsrc[2][2] = {{0.f, 0.f}, {0.f, 0.f}};
        float ldst[2][2] = {{0.f, 0.f}, {0.f, 0.f}};
        const int head = (bcol + warpN * 64) >> 6;
        #pragma unroll
        for (int mt = 0; mt < 2; mt++) {
            #pragma unroll
            for (int nt = 0; nt < 8; nt++) {
                int n_loc = warpN * 64 + nt * 8 + 2 * (lane & 3);
                int gcol = bcol + n_loc;
                int row0 = blockRow + warpM * 32 + mt * 16 + (lane >> 2);
                float c0 = acc[mt][nt][0], c1 = acc[mt][nt][1];
                float c2 = acc[mt][nt][2], c3 = acc[mt][nt][3];
                if (row0 < NNODES)
                    *reinterpret_cast<__half2*>(&g_hh[(size_t)row0 * DIM + gcol]) =
                        __floats2half2_rn(c0, c1);
                if (row0 + 8 < NNODES)
                    *reinterpret_cast<__half2*>(&g_hh[(size_t)(row0 + 8) * DIM + gcol]) =
                        __floats2half2_rn(c2, c3);
                int cl = gcol & 63;
                float as0 = __ldg(&a_src[head * 64 + cl]);
                float as1 = __ldg(&a_src[head * 64 + cl + 1]);
                float ad0 = __ldg(&a_dst[head * 64 + cl]);
                float ad1 = __ldg(&a_dst[head * 64 + cl + 1]);
                lsrc[mt][0] = fmaf(c0, as0, fmaf(c1, as1, lsrc[mt][0]));
                lsrc[mt][1] = fmaf(c2, as0, fmaf(c3, as1, lsrc[mt][1]));
                ldst[mt][0] = fmaf(c0, ad0, fmaf(c1, ad1, ldst[mt][0]));
                ldst[mt][1] = fmaf(c2, ad0, fmaf(c3, ad1, ldst[mt][1]));
            }
        }
        #pragma unroll
        for (int mt = 0; mt < 2; mt++)
            #pragma unroll
            for (int rh = 0; rh < 2; rh++) {
                float s = lsrc[mt][rh];
                float d = ldst[mt][rh];
                s += __shfl_xor_sync(0xffffffffu, s, 1);
                s += __shfl_xor_sync(0xffffffffu, s, 2);
                d += __shfl_xor_sync(0xffffffffu, d, 1);
                d += __shfl_xor_sync(0xffffffffu, d, 2);
                int row = blockRow + warpM * 32 + mt * 16 + rh * 8 + (lane >> 2);
                if ((lane & 3) == 0 && row < NNODES) {
                    g_al_src[row * NH + head] = s;
                    g_al_dst[row * NH + head] = d;
                }
            }
    } else {
        #pragma unroll
        for (int mt = 0; mt < 2; mt++) {
            #pragma unroll
            for (int nt = 0; nt < 8; nt++) {
                int n_loc = warpN * 64 + nt * 8 + 2 * (lane & 3);
                int gcol = (bcol - 256) + n_loc;
                int row0 = blockRow + warpM * 32 + mt * 16 + (lane >> 2);
                if (row0 < NNODES) {
                    float2 v = make_float2(acc[mt][nt][0], acc[mt][nt][1]);
                    *reinterpret_cast<float2*>(&g_r[(size_t)row0 * DIM + gcol]) = v;
                }
                if (row0 + 8 < NNODES) {
                    float2 v = make_float2(acc[mt][nt][2], acc[mt][nt][3]);
                    *reinterpret_cast<float2*>(&g_r[(size_t)(row0 + 8) * DIM + gcol]) = v;
                }
            }
        }
    }
}

// ---------------- CSR build ----------------
__global__ void hist_kernel(const void* __restrict__ ei) {
    int i = blockIdx.x * blockDim.x + threadIdx.x;
    if (i < NEDGES) {
        int d = edge_at(ei, (long long)NEDGES + i);
        atomicAdd(&g_count[d], 1);
    }
}

__global__ __launch_bounds__(SCAN_CHUNK) void scan1_kernel() {
    __shared__ int s[SCAN_CHUNK];
    int i = blockIdx.x * SCAN_CHUNK + threadIdx.x;
    int v = (i < NNODES) ? g_count[i] : 0;
    s[threadIdx.x] = v;
    __syncthreads();
    for (int off = 1; off < SCAN_CHUNK; off <<= 1) {
        int t = s[threadIdx.x];
        int u = (threadIdx.x >= off) ? s[threadIdx.x - off] : 0;
        __syncthreads();
        s[threadIdx.x] = t + u;
        __syncthreads();
    }
    if (i < NNODES) g_scan[i] = s[threadIdx.x];
    if (threadIdx.x == SCAN_CHUNK - 1) g_bsum[blockIdx.x] = s[SCAN_CHUNK - 1];
}

__global__ void scan2_kernel() {
    if (threadIdx.x == 0 && blockIdx.x == 0) {
        int run = 0;
        for (int b = 0; b < NCHUNK; b++) { g_boff[b] = run; run += g_bsum[b]; }
    }
}

__global__ void scan3_kernel() {
    int i = blockIdx.x * blockDim.x + threadIdx.x;
    if (i >= NNODES) return;
    int cnt = g_count[i];
    int incl = g_scan[i] + g_boff[i / SCAN_CHUNK];
    int start = incl - cnt;
    g_rowptr[i] = start;
    g_cursor[i] = start + 1;
    g_csr_src[start] = i;
    float4 es = *reinterpret_cast<const float4*>(&g_al_src[i * NH]);
    float4 ed = *reinterpret_cast<const float4*>(&g_al_dst[i * NH]);
    float4 e = make_float4(lrelu(es.x + ed.x), lrelu(es.y + ed.y),
                           lrelu(es.z + ed.z), lrelu(es.w + ed.w));
    *reinterpret_cast<float4*>(&g_csr_e[(size_t)start * NH]) = e;
    if (i == NNODES - 1) g_rowptr[NNODES] = start + cnt;
}

__global__ void scatter_kernel(const void* __restrict__ ei) {
    int i = blockIdx.x * blockDim.x + threadIdx.x;
    if (i >= NEDGES) return;
    int s = edge_at(ei, i);
    int d = edge_at(ei, (long long)NEDGES + i);
    int pos = atomicAdd(&g_cursor[d], 1);
    g_csr_src[pos] = s;
    float4 es = *reinterpret_cast<const float4*>(&g_al_src[s * NH]);
    float4 ed = *reinterpret_cast<const float4*>(&g_al_dst[d * NH]);
    float4 e = make_float4(lrelu(es.x + ed.x), lrelu(es.y + ed.y),
                           lrelu(es.z + ed.z), lrelu(es.w + ed.w));
    *reinterpret_cast<float4*>(&g_csr_e[(size_t)pos * NH]) = e;
}

// ---------------- fused softmax + aggregate + residual + LayerNorm ----------
#define AGG_CH 128
__global__ __launch_bounds__(128) void aggregate_kernel(
    const float* __restrict__ bias_gat, const float* __restrict__ b_res,
    const float* __restrict__ gamma, const float* __restrict__ beta,
    float* __restrict__ out)
{
    int v = blockIdx.x;
    int tid = threadIdx.x;
    int start = g_rowptr[v];
    int deg = g_rowptr[v + 1] - start;

    __shared__ float s_m[NH], s_inv[NH];
    __shared__ int   s_src[AGG_CH];
    __shared__ float s_alpha[AGG_CH * NH];
    __shared__ float s_s[4], s_q[4];

    if (tid < 32) {
        float m0 = -1e30f, m1 = -1e30f, m2 = -1e30f, m3 = -1e30f;
        for (int j = tid; j < deg; j += 32) {
            float4 e = *reinterpret_cast<const float4*>(&g_csr_e[(size_t)(start + j) * NH]);
            m0 = fmaxf(m0, e.x); m1 = fmaxf(m1, e.y);
            m2 = fmaxf(m2, e.z); m3 = fmaxf(m3, e.w);
        }
        #pragma unroll
        for (int o = 16; o > 0; o >>= 1) {
            m0 = fmaxf(m0, __shfl_xor_sync(0xffffffffu, m0, o));
            m1 = fmaxf(m1, __shfl_xor_sync(0xffffffffu, m1, o));
            m2 = fmaxf(m2, __shfl_xor_sync(0xffffffffu, m2, o));
            m3 = fmaxf(m3, __shfl_xor_sync(0xffffffffu, m3, o));
        }
        float d0 = 0.f, d1 = 0.f, d2 = 0.f, d3 = 0.f;
        for (int j = tid; j < deg; j += 32) {
            float4 e = *reinterpret_cast<const float4*>(&g_csr_e[(size_t)(start + j) * NH]);
            d0 += expf(e.x - m0); d1 += expf(e.y - m1);
            d2 += expf(e.z - m2); d3 += expf(e.w - m3);
        }
        #pragma unroll
        for (int o = 16; o > 0; o >>= 1) {
            d0 += __shfl_xor_sync(0xffffffffu, d0, o);
            d1 += __shfl_xor_sync(0xffffffffu, d1, o);
            d2 += __shfl_xor_sync(0xffffffffu, d2, o);
            d3 += __shfl_xor_sync(0xffffffffu, d3, o);
        }
        if (tid == 0) {
            s_m[0] = m0; s_m[1] = m1; s_m[2] = m2; s_m[3] = m3;
            s_inv[0] = 1.f / (d0 + 1e-16f);
            s_inv[1] = 1.f / (d1 + 1e-16f);
            s_inv[2] = 1.f / (d2 + 1e-16f);
            s_inv[3] = 1.f / (d3 + 1e-16f);
        }
    }
    __syncthreads();

    const int hd = tid >> 5;
    float2 acc = make_float2(0.f, 0.f);
    const __half2* hh2 = reinterpret_cast<const __half2*>(g_hh);

    for (int c0 = 0; c0 < deg; c0 += AGG_CH) {
        int len = min(AGG_CH, deg - c0);
        if (tid < len) s_src[tid] = g_csr_src[start + c0 + tid];
        for (int t = tid; t < len * NH; t += 128) {
            int j = t >> 2, h = t & 3;
            s_alpha[t] = expf(g_csr_e[(size_t)(start + c0 + j) * NH + h] - s_m[h]) * s_inv[h];
        }
        __syncthreads();

        int j = 0;
        for (; j + 4 <= len; j += 4) {
            int sa = s_src[j], sb = s_src[j+1], sc = s_src[j+2], sd = s_src[j+3];
            float a0 = s_alpha[((j    ) << 2) | hd];
            float a1 = s_alpha[((j + 1) << 2) | hd];
            float a2 = s_alpha[((j + 2) << 2) | hd];
            float a3 = s_alpha[((j + 3) << 2) | hd];
            float2 h0 = __half22float2(hh2[(size_t)sa * 128 + tid]);
            float2 h1 = __half22float2(hh2[(size_t)sb * 128 + tid]);
            float2 h2 = __half22float2(hh2[(size_t)sc * 128 + tid]);
            float2 h3 = __half22float2(hh2[(size_t)sd * 128 + tid]);
            acc.x = fmaf(a0, h0.x, acc.x); acc.y = fmaf(a0, h0.y, acc.y);
            acc.x = fmaf(a1, h1.x, acc.x); acc.y = fmaf(a1, h1.y, acc.y);
            acc.x = fmaf(a2, h2.x, acc.x); acc.y = fmaf(a2, h2.y, acc.y);
            acc.x = fmaf(a3, h3.x, acc.x); acc.y = fmaf(a3, h3.y, acc.y);
        }
        for (; j < len; j++) {
            float a = s_alpha[(j << 2) | hd];
            float2 hv = __half22float2(hh2[(size_t)s_src[j] * 128 + tid]);
            acc.x = fmaf(a, hv.x, acc.x);
            acc.y = fmaf(a, hv.y, acc.y);
        }
        __syncthreads();
    }

    float2 bg = *reinterpret_cast<const float2*>(&bias_gat[2 * tid]);
    float2 br = *reinterpret_cast<const float2*>(&b_res[2 * tid]);
    float2 rr = *reinterpret_cast<const float2*>(&g_r[(size_t)v * DIM + 2 * tid]);
    float y0 = acc.x + bg.x + rr.x + br.x;
    float y1 = acc.y + bg.y + rr.y + br.y;

    float sum = y0 + y1, sq = y0 * y0 + y1 * y1;
    #pragma unroll
    for (int o = 16; o > 0; o >>= 1) {
        sum += __shfl_xor_sync(0xffffffffu, sum, o);
        sq  += __shfl_xor_sync(0xffffffffu, sq, o);
    }
    int wid = tid >> 5, lane = tid & 31;
    if (lane == 0) { s_s[wid] = sum; s_q[wid] = sq; }
    __syncthreads();
    if (tid == 0) {
        float a = s_s[0] + s_s[1] + s_s[2] + s_s[3];
        float b = s_q[0] + s_q[1] + s_q[2] + s_q[3];
        float mu = a * (1.f / DIM);
        float var = b * (1.f / DIM) - mu * mu;
        s_s[0] = mu;
        s_q[0] = rsqrtf(var + LN_EPS);
    }
    __syncthreads();
    float mu = s_s[0], rstd = s_q[0];
    float2 gm = *reinterpret_cast<const float2*>(&gamma[2 * tid]);
    float2 bt = *reinterpret_cast<const float2*>(&beta[2 * tid]);
    float2 o2 = make_float2(gm.x * (y0 - mu) * rstd + bt.x,
                            gm.y * (y1 - mu) * rstd + bt.y);
    *reinterpret_cast<float2*>(&out[(size_t)v * DIM + 2 * tid]) = o2;
}

// ---------------- launch ----------------
extern "C" void kernel_launch(void* const* d_in, const int* in_sizes, int n_in,
                              void* d_out, int out_size)
{
    const float* x        = (const float*)d_in[0];
    const void*  ei       = d_in[1];
    const float* W        = (const float*)d_in[2];
    const float* a_src    = (const float*)d_in[3];
    const float* a_dst    = (const float*)d_in[4];
    const float* bias_gat = (const float*)d_in[5];
    const float* W_res    = (const float*)d_in[6];
    const float* b_res    = (const float*)d_in[7];
    const float* gamma    = (const float*)d_in[8];
    const float* beta     = (const float*)d_in[9];
    float* out = (float*)d_out;

    static int smem_set = 0;
    const int SMEM = 2 * STAGE_BYTES;  // 81920
    if (!smem_set) {
        cudaFuncSetAttribute(bf16_gemm_kernel, cudaFuncAttributeMaxDynamicSharedMemorySize, SMEM);
        smem_set = 1;
    }

    detect_init_kernel<<<(NNODES + 255) / 256, 256>>>((const int*)ei);
    split_x_kernel<<<((long long)MPAD * DIM / 4 + 255) / 256, 256>>>(x);
    split_w_kernel<<<(512 * 256 + 255) / 256, 256>>>(W, W_res);

    dim3 ggrid(4, MPAD / 128);
    bf16_gemm_kernel<<<ggrid, 256, SMEM>>>(a_src, a_dst);

    hist_kernel<<<(NEDGES + 255) / 256, 256>>>(ei);
    scan1_kernel<<<NCHUNK, SCAN_CHUNK>>>();
    scan2_kernel<<<1, 32>>>();
    scan3_kernel<<<(NNODES + 255) / 256, 256>>>();
    scatter_kernel<<<(NEDGES + 255) / 256, 256>>>(ei);

    aggregate_kernel<<<NNODES, 128>>>(bias_gat, b_res, gamma, beta, out);
}